// round 3
// baseline (speedup 1.0000x reference)
#include <cuda_runtime.h>
#include <math.h>

// Fused blockwise-dequant GEMM: C[M,N] = X[M,K] * W[N,K]^T
// W[n,k] = (Q[n,k] - 127.5) / 127.5 * absmax[n, k/256]
//
// 128x128x16 tiles, 256 threads, 8x8 per-thread micro-tile,
// accumulators packed as f32x2 pairs driven by PTX fma.rn.f32x2
// (2 FMAs per issue slot on the fma pipe; bit-identical to scalar FFMA).

#define BM 128
#define BN 128
#define BK 16
#define TM 8
#define TN 8
#define THREADS 256

typedef unsigned long long ull;

__device__ __forceinline__ ull pack_dup(float a) {
    ull r;
    asm("mov.b64 %0, {%1, %1};" : "=l"(r) : "f"(a));
    return r;
}

__device__ __forceinline__ void fma2(ull& acc, ull a, ull b) {
    asm("fma.rn.f32x2 %0, %1, %2, %0;" : "+l"(acc) : "l"(a), "l"(b));
}

__device__ __forceinline__ void unpack2(ull v, float& lo, float& hi) {
    asm("mov.b64 {%0, %1}, %2;" : "=f"(lo), "=f"(hi) : "l"(v));
}

__global__ __launch_bounds__(THREADS, 2)
void dq_gemm_kernel(const float* __restrict__ X,
                    const int* __restrict__ Q,
                    const float* __restrict__ AM,
                    float* __restrict__ C,
                    int M, int N, int K) {
    // +4 padding keeps float4 alignment (132*4B = 528B, multiple of 16)
    // while breaking most store-phase bank conflicts.
    __shared__ float As[BK][BM + 4];   // X^T tile: As[k][m]
    __shared__ float Bs[BK][BN + 4];   // W^T tile: Bs[k][n]

    const int tid = threadIdx.x;
    const int tx = tid & 15;           // n-direction (0..15)
    const int ty = tid >> 4;           // m-direction (0..15)
    const int m0 = blockIdx.x * BM;
    const int n0 = blockIdx.y * BN;
    const int nblk = K >> 8;           // absmax blocks per row (K/256)

    ull acc[TM][TN / 2];
    #pragma unroll
    for (int i = 0; i < TM; i++)
        #pragma unroll
        for (int j = 0; j < TN / 2; j++)
            acc[i][j] = 0ull;

    for (int k0 = 0; k0 < K; k0 += BK) {
        const int amIdx = k0 >> 8;

        // ---- load X tile [BM, BK] -> As[k][m] (transposed) ----
        #pragma unroll
        for (int t = 0; t < 2; t++) {
            int idx = tid + t * THREADS;          // 0..511
            int row = idx >> 2;                   // 0..127
            int c   = (idx & 3) << 2;             // 0,4,8,12
            float4 v = *(const float4*)(X + (size_t)(m0 + row) * K + k0 + c);
            As[c + 0][row] = v.x;
            As[c + 1][row] = v.y;
            As[c + 2][row] = v.z;
            As[c + 3][row] = v.w;
        }

        // ---- load + dequant W tile [BN, BK] -> Bs[k][n] (transposed) ----
        #pragma unroll
        for (int t = 0; t < 2; t++) {
            int idx = tid + t * THREADS;
            int row = idx >> 2;                   // 0..127 (vocab row within tile)
            int c   = (idx & 3) << 2;
            int4 q = *(const int4*)(Q + (size_t)(n0 + row) * K + k0 + c);
            float s = __ldg(AM + (size_t)(n0 + row) * nblk + amIdx) * (1.0f / 127.5f);
            Bs[c + 0][row] = ((float)q.x - 127.5f) * s;
            Bs[c + 1][row] = ((float)q.y - 127.5f) * s;
            Bs[c + 2][row] = ((float)q.z - 127.5f) * s;
            Bs[c + 3][row] = ((float)q.w - 127.5f) * s;
        }

        __syncthreads();

        // ---- 8x8 micro-tile outer products, FFMA2 packed along n ----
        #pragma unroll
        for (int k = 0; k < BK; k++) {
            float4 a0 = *(const float4*)&As[k][ty * TM];
            float4 a1 = *(const float4*)&As[k][ty * TM + 4];
            const ull* bp = (const ull*)&Bs[k][tx * TN];
            ull b0 = bp[0], b1 = bp[1], b2 = bp[2], b3 = bp[3];

            ull ad[TM];
            ad[0] = pack_dup(a0.x); ad[1] = pack_dup(a0.y);
            ad[2] = pack_dup(a0.z); ad[3] = pack_dup(a0.w);
            ad[4] = pack_dup(a1.x); ad[5] = pack_dup(a1.y);
            ad[6] = pack_dup(a1.z); ad[7] = pack_dup(a1.w);

            #pragma unroll
            for (int i = 0; i < TM; i++) {
                fma2(acc[i][0], ad[i], b0);
                fma2(acc[i][1], ad[i], b1);
                fma2(acc[i][2], ad[i], b2);
                fma2(acc[i][3], ad[i], b3);
            }
        }

        __syncthreads();
    }

    // ---- epilogue: unpack pairs, vectorized float4 stores ----
    #pragma unroll
    for (int i = 0; i < TM; i++) {
        float o[8];
        unpack2(acc[i][0], o[0], o[1]);
        unpack2(acc[i][1], o[2], o[3]);
        unpack2(acc[i][2], o[4], o[5]);
        unpack2(acc[i][3], o[6], o[7]);
        float4* cp = (float4*)(C + (size_t)(m0 + ty * TM + i) * N + n0 + tx * TN);
        cp[0] = make_float4(o[0], o[1], o[2], o[3]);
        cp[1] = make_float4(o[4], o[5], o[6], o[7]);
    }
}

extern "C" void kernel_launch(void* const* d_in, const int* in_sizes, int n_in,
                              void* d_out, int out_size) {
    const float* X  = (const float*)d_in[0];   // x: [B,S,D] f32 -> [M,K]
    const int*   Q  = (const int*)d_in[1];     // q_weight: [V,D] int32 -> [N,K]
    const float* AM = (const float*)d_in[2];   // absmax: [V, D/256] f32

    // Derive dims: s0 = M*K, s1 = N*K, out = M*N  =>  K = sqrt(s0*s1/out)
    double s0 = (double)in_sizes[0];
    double s1 = (double)in_sizes[1];
    double so = (double)out_size;
    int K = (int)(sqrt(s0 * s1 / so) + 0.5);
    int M = (int)(s0 / K + 0.5);
    int N = (int)(s1 / K + 0.5);

    // Grid ordered (m-tiles, n-tiles): a wave spans all m-tiles of a few
    // n-stripes, so x (32 MB) stays L2-resident while q_weight streams.
    dim3 grid(M / BM, N / BN);
    dq_gemm_kernel<<<grid, THREADS>>>(X, Q, AM, (float*)d_out, M, N, K);
}

// round 5
// speedup vs baseline: 3.2804x; 3.2804x over previous
#include <cuda_runtime.h>
#include <cuda_fp16.h>
#include <math.h>
#include <stdint.h>

typedef unsigned int u32;

// Fixed dataset shapes: M=4096, K=2048, N=32000
#define MAX_M 4096
#define MAX_K 2048
#define MAX_V 32000

// Static device scratch (allocation-free rule)
__device__ __half g_XH[(size_t)MAX_M * MAX_K];
__device__ __half g_XL[(size_t)MAX_M * MAX_K];
__device__ __half g_WH[(size_t)MAX_V * MAX_K];
__device__ __half g_WL[(size_t)MAX_V * MAX_K];

// ---------------- PTX helpers (all compute_80-baseline) ----------------

static __device__ __forceinline__ u32 smem_u32(const void* p) {
    u32 a;
    asm("{ .reg .u64 t; cvta.to.shared.u64 t, %1; cvt.u32.u64 %0, t; }"
        : "=r"(a) : "l"(p));
    return a;
}

static __device__ __forceinline__ void cp16(u32 d, const void* g) {
    asm volatile("cp.async.cg.shared.global [%0], [%1], 16;"
                 :: "r"(d), "l"(g) : "memory");
}
static __device__ __forceinline__ void cp_commit() {
    asm volatile("cp.async.commit_group;" ::: "memory");
}
static __device__ __forceinline__ void cp_wait1() {
    asm volatile("cp.async.wait_group 1;" ::: "memory");
}

static __device__ __forceinline__ void ldsm4(u32 a, u32& r0, u32& r1, u32& r2, u32& r3) {
    asm volatile("ldmatrix.sync.aligned.m8n8.x4.shared.b16 {%0,%1,%2,%3}, [%4];"
                 : "=r"(r0), "=r"(r1), "=r"(r2), "=r"(r3) : "r"(a));
}
static __device__ __forceinline__ void ldsm2(u32 a, u32& r0, u32& r1) {
    asm volatile("ldmatrix.sync.aligned.m8n8.x2.shared.b16 {%0,%1}, [%2];"
                 : "=r"(r0), "=r"(r1) : "r"(a));
}

static __device__ __forceinline__ void mma16816(float* c,
                                                u32 a0, u32 a1, u32 a2, u32 a3,
                                                u32 b0, u32 b1) {
    asm volatile(
        "mma.sync.aligned.m16n8k16.row.col.f32.f16.f16.f32 "
        "{%0,%1,%2,%3}, {%4,%5,%6,%7}, {%8,%9}, {%0,%1,%2,%3};"
        : "+f"(c[0]), "+f"(c[1]), "+f"(c[2]), "+f"(c[3])
        : "r"(a0), "r"(a1), "r"(a2), "r"(a3), "r"(b0), "r"(b1));
}

// XOR swizzle for 64B rows (BK=32 f16): 16B chunk index XORed with row bits.
// Conflict-free for cp.async STS.128 and all ldmatrix phases.
static __device__ __forceinline__ u32 swz(int row, int chunk) {
    return (u32)(row * 64 + ((chunk ^ ((row >> 1) & 3)) << 4));
}

// ---------------- Pre-pass kernels ----------------

__global__ void split_x_kernel(const float* __restrict__ X, int total4) {
    int i = blockIdx.x * 256 + threadIdx.x;
    if (i >= total4) return;
    float4 v = ((const float4*)X)[i];
    float f[4] = {v.x, v.y, v.z, v.w};
    __half h[4], l[4];
#pragma unroll
    for (int j = 0; j < 4; j++) {
        h[j] = __float2half_rn(f[j]);
        l[j] = __float2half_rn(f[j] - __half2float(h[j]));
    }
    ((uint2*)g_XH)[i] = *(uint2*)h;
    ((uint2*)g_XL)[i] = *(uint2*)l;
}

__global__ void dequant_w_kernel(const int* __restrict__ Q,
                                 const float* __restrict__ AM,
                                 int total4, int kdiv4, int nblk) {
    int i = blockIdx.x * 256 + threadIdx.x;
    if (i >= total4) return;
    int row = i / kdiv4;
    int c4 = i - row * kdiv4;
    int kblk = (c4 * 4) >> 8;
    float s = AM[(size_t)row * nblk + kblk] * (1.0f / 127.5f);
    int4 q = ((const int4*)Q)[i];
    float f[4] = {((float)q.x - 127.5f) * s, ((float)q.y - 127.5f) * s,
                  ((float)q.z - 127.5f) * s, ((float)q.w - 127.5f) * s};
    __half h[4], l[4];
#pragma unroll
    for (int j = 0; j < 4; j++) {
        h[j] = __float2half_rn(f[j]);
        l[j] = __float2half_rn(f[j] - __half2float(h[j]));
    }
    ((uint2*)g_WH)[i] = *(uint2*)h;
    ((uint2*)g_WL)[i] = *(uint2*)l;
}

// ---------------- Main GEMM: mma.sync fp16x3 ----------------
// C[M,N] = X[M,K] * W[N,K]^T with X = XH+XL, W = WH+WL (drop XL*WL).
// CTA tile 128x128, BK=32, 8 warps (2x4, 64x32 each), 2-stage cp.async.

#define BM 128
#define BN 128
#define BK 32
#define THREADS 256
#define TILE_B (BM * 64)          // 8 KB per fp16 [128][32] tile
#define STAGE_B (4 * TILE_B)      // AH, AL, WH, WL = 32 KB
#define SMEM_B (2 * STAGE_B)      // 64 KB

__global__ __launch_bounds__(THREADS)
void gemm_hmma(float* __restrict__ C, int M, int N, int K) {
    extern __shared__ char sm[];
    const u32 sb = smem_u32(sm);
    const int tid = threadIdx.x;
    const int wid = tid >> 5;
    const int lane = tid & 31;
    const int m0 = blockIdx.x * BM;
    const int n0 = blockIdx.y * BN;
    const int warp_m = wid >> 2;      // 0..1
    const int warp_n = wid & 3;       // 0..3

    const size_t baseX = (size_t)m0 * K;
    const size_t baseW = (size_t)n0 * K;

    // cp.async mapping (per tile, 2 chunks per thread)
    const int r0i = tid >> 2;                 // rows tid/4, +64 for t=1
    const int kc0 = tid & 3;

    // ldmatrix lane decode
    const int matA = lane >> 3;               // 0..3
    const int rowA_base = warp_m * 64 + ((matA & 1) << 3) + (lane & 7);
    const int cA_sel = matA >> 1;             // k-half within k16
    const int matB = (lane >> 3) & 1;
    const int rowB_base = warp_n * 32 + (lane & 7);

    float acc[4][4][4];
#pragma unroll
    for (int i = 0; i < 4; i++)
#pragma unroll
        for (int j = 0; j < 4; j++)
#pragma unroll
            for (int e = 0; e < 4; e++) acc[i][j][e] = 0.0f;

    const int NK = K / BK;   // 64

    // ---- prefetch stage 0 ----
    {
        const int k0 = 0;
        const u32 st = sb;
#pragma unroll
        for (int t = 0; t < 2; t++) {
            int row = r0i + t * 64;
            u32 d = st + swz(row, kc0);
            size_t gx = baseX + (size_t)row * K + k0 + kc0 * 8;
            size_t gw = baseW + (size_t)row * K + k0 + kc0 * 8;
            cp16(d, g_XH + gx);
            cp16(d + TILE_B, g_XL + gx);
            cp16(d + 2 * TILE_B, g_WH + gw);
            cp16(d + 3 * TILE_B, g_WL + gw);
        }
        cp_commit();
    }

    for (int kt = 0; kt < NK; kt++) {
        const int s = kt & 1;

        // prefetch stage kt+1
        if (kt + 1 < NK) {
            const int k0 = (kt + 1) * BK;
            const u32 st = sb + (s ^ 1) * STAGE_B;
#pragma unroll
            for (int t = 0; t < 2; t++) {
                int row = r0i + t * 64;
                u32 d = st + swz(row, kc0);
                size_t gx = baseX + (size_t)row * K + k0 + kc0 * 8;
                size_t gw = baseW + (size_t)row * K + k0 + kc0 * 8;
                cp16(d, g_XH + gx);
                cp16(d + TILE_B, g_XL + gx);
                cp16(d + 2 * TILE_B, g_WH + gw);
                cp16(d + 3 * TILE_B, g_WL + gw);
            }
        }
        cp_commit();
        cp_wait1();            // stage kt data resident
        __syncthreads();

        // ---- compute on stage s ----
        const u32 stAH = sb + s * STAGE_B;
        const u32 stAL = stAH + TILE_B;
        const u32 stBH = stAH + 2 * TILE_B;
        const u32 stBL = stAH + 3 * TILE_B;

#pragma unroll
        for (int ks = 0; ks < 2; ks++) {
            u32 bh[4][2], bl[4][2];
#pragma unroll
            for (int nj = 0; nj < 4; nj++) {
                u32 off = swz(rowB_base + nj * 8, ks * 2 + matB);
                ldsm2(stBH + off, bh[nj][0], bh[nj][1]);
                ldsm2(stBL + off, bl[nj][0], bl[nj][1]);
            }
#pragma unroll
            for (int mi = 0; mi < 4; mi++) {
                u32 off = swz(rowA_base + mi * 16, ks * 2 + cA_sel);
                u32 ah0, ah1, ah2, ah3, al0, al1, al2, al3;
                ldsm4(stAH + off, ah0, ah1, ah2, ah3);
                ldsm4(stAL + off, al0, al1, al2, al3);
#pragma unroll
                for (int nj = 0; nj < 4; nj++) {
                    mma16816(acc[mi][nj], ah0, ah1, ah2, ah3, bh[nj][0], bh[nj][1]);
                    mma16816(acc[mi][nj], al0, al1, al2, al3, bh[nj][0], bh[nj][1]);
                    mma16816(acc[mi][nj], ah0, ah1, ah2, ah3, bl[nj][0], bl[nj][1]);
                }
            }
        }
        __syncthreads();
    }

    // ---- epilogue: direct float2 stores ----
    const int er = m0 + warp_m * 64 + (lane >> 2);
    const int ec = n0 + warp_n * 32 + (lane & 3) * 2;
#pragma unroll
    for (int mi = 0; mi < 4; mi++) {
#pragma unroll
        for (int nj = 0; nj < 4; nj++) {
            float* p0 = C + (size_t)(er + mi * 16) * N + ec + nj * 8;
            float* p1 = C + (size_t)(er + mi * 16 + 8) * N + ec + nj * 8;
            *(float2*)p0 = make_float2(acc[mi][nj][0], acc[mi][nj][1]);
            *(float2*)p1 = make_float2(acc[mi][nj][2], acc[mi][nj][3]);
        }
    }
}

// ---------------- launch ----------------

extern "C" void kernel_launch(void* const* d_in, const int* in_sizes, int n_in,
                              void* d_out, int out_size) {
    const float* X  = (const float*)d_in[0];   // [M, K] fp32
    const int*   Q  = (const int*)d_in[1];     // [N, K] int32 codes
    const float* AM = (const float*)d_in[2];   // [N, K/256] fp32

    double s0 = (double)in_sizes[0];
    double s1 = (double)in_sizes[1];
    double so = (double)out_size;
    int K = (int)(sqrt(s0 * s1 / so) + 0.5);
    int M = (int)(s0 / K + 0.5);
    int N = (int)(s1 / K + 0.5);
    int nblk = K >> 8;

    int xt4 = (M * K) / 4;
    split_x_kernel<<<(xt4 + 255) / 256, 256>>>(X, xt4);
    long long wt4ll = ((long long)N * K) / 4;
    int wt4 = (int)wt4ll;
    dequant_w_kernel<<<(int)((wt4 + 255) / 256), 256>>>(Q, AM, wt4, K / 4, nblk);

    cudaFuncSetAttribute(gemm_hmma, cudaFuncAttributeMaxDynamicSharedMemorySize, SMEM_B);
    dim3 grid(M / BM, N / BN);   // m fastest: W n-stripe shared via L2 within a wave
    gemm_hmma<<<grid, THREADS, SMEM_B>>>((float*)d_out, M, N, K);
}

// round 6
// speedup vs baseline: 3.5540x; 1.0834x over previous
#include <cuda_runtime.h>
#include <cuda_fp16.h>
#include <math.h>
#include <stdint.h>

typedef unsigned int u32;

// Fixed dataset shapes: M=4096, K=2048, N=32000
#define MAX_M 4096
#define MAX_K 2048
#define MAX_V 32000
#define MAX_NBLK (MAX_K / 256)

// Static device scratch (allocation-free rule)
__device__ __half g_XH[(size_t)MAX_M * MAX_K];
__device__ __half g_XL[(size_t)MAX_M * MAX_K];
__device__ __half g_WQ[(size_t)MAX_V * MAX_K];   // exact codes (q - 127.5) in fp16
__device__ float  g_S[(size_t)MAX_NBLK * MAX_V]; // transposed scales absmax/127.5

// ---------------- PTX helpers (compute_80 baseline, safe on sm_103 family) ----

static __device__ __forceinline__ u32 smem_u32(const void* p) {
    u32 a;
    asm("{ .reg .u64 t; cvta.to.shared.u64 t, %1; cvt.u32.u64 %0, t; }"
        : "=r"(a) : "l"(p));
    return a;
}

static __device__ __forceinline__ void cp16(u32 d, const void* g) {
    asm volatile("cp.async.cg.shared.global [%0], [%1], 16;"
                 :: "r"(d), "l"(g) : "memory");
}
static __device__ __forceinline__ void cp_commit() {
    asm volatile("cp.async.commit_group;" ::: "memory");
}
static __device__ __forceinline__ void cp_wait2() {
    asm volatile("cp.async.wait_group 2;" ::: "memory");
}

static __device__ __forceinline__ void ldsm4(u32 a, u32& r0, u32& r1, u32& r2, u32& r3) {
    asm volatile("ldmatrix.sync.aligned.m8n8.x4.shared.b16 {%0,%1,%2,%3}, [%4];"
                 : "=r"(r0), "=r"(r1), "=r"(r2), "=r"(r3) : "r"(a));
}
static __device__ __forceinline__ void ldsm2(u32 a, u32& r0, u32& r1) {
    asm volatile("ldmatrix.sync.aligned.m8n8.x2.shared.b16 {%0,%1}, [%2];"
                 : "=r"(r0), "=r"(r1) : "r"(a));
}

static __device__ __forceinline__ void mma16816(float* c,
                                                u32 a0, u32 a1, u32 a2, u32 a3,
                                                u32 b0, u32 b1) {
    asm volatile(
        "mma.sync.aligned.m16n8k16.row.col.f32.f16.f16.f32 "
        "{%0,%1,%2,%3}, {%4,%5,%6,%7}, {%8,%9}, {%0,%1,%2,%3};"
        : "+f"(c[0]), "+f"(c[1]), "+f"(c[2]), "+f"(c[3])
        : "r"(a0), "r"(a1), "r"(a2), "r"(a3), "r"(b0), "r"(b1));
}

// XOR swizzle for 64B rows (BK=32 f16): conflict-free STS.128 + ldmatrix.
static __device__ __forceinline__ u32 swz(int row, int chunk) {
    return (u32)(row * 64 + ((chunk ^ ((row >> 1) & 3)) << 4));
}

// ---------------- Pre-pass kernels ----------------

// X fp32 -> (XH + XL) fp16 pair (residual split, 22-bit coverage)
__global__ void split_x_kernel(const float* __restrict__ X, int total4) {
    int i = blockIdx.x * 256 + threadIdx.x;
    if (i >= total4) return;
    float4 v = ((const float4*)X)[i];
    float f[4] = {v.x, v.y, v.z, v.w};
    __half h[4], l[4];
#pragma unroll
    for (int j = 0; j < 4; j++) {
        h[j] = __float2half_rn(f[j]);
        l[j] = __float2half_rn(f[j] - __half2float(h[j]));
    }
    ((uint2*)g_XH)[i] = *(uint2*)h;
    ((uint2*)g_XL)[i] = *(uint2*)l;
}

// Q int32 codes -> fp16 (q - 127.5), EXACT (8-bit mantissa fits fp16). 8/thread.
__global__ void prep_w_kernel(const int* __restrict__ Q, int total8) {
    int i = blockIdx.x * 256 + threadIdx.x;
    if (i >= total8) return;
    int4 a = ((const int4*)Q)[2 * i];
    int4 b = ((const int4*)Q)[2 * i + 1];
    __half h[8];
    h[0] = __float2half_rn((float)a.x - 127.5f);
    h[1] = __float2half_rn((float)a.y - 127.5f);
    h[2] = __float2half_rn((float)a.z - 127.5f);
    h[3] = __float2half_rn((float)a.w - 127.5f);
    h[4] = __float2half_rn((float)b.x - 127.5f);
    h[5] = __float2half_rn((float)b.y - 127.5f);
    h[6] = __float2half_rn((float)b.z - 127.5f);
    h[7] = __float2half_rn((float)b.w - 127.5f);
    ((uint4*)g_WQ)[i] = *(uint4*)h;
}

// Transpose absmax [N, nblk] -> g_S [nblk, N] with 1/127.5 folded in.
__global__ void prep_s_kernel(const float* __restrict__ AM, int N, int nblk) {
    int i = blockIdx.x * 256 + threadIdx.x;
    if (i >= N * nblk) return;
    int kb = i / N;
    int n = i - kb * N;
    g_S[i] = AM[(size_t)n * nblk + kb] * (1.0f / 127.5f);
}

// ---------------- Main GEMM: mma.sync, exact-W + split-X (2 terms) ----------
// CTA tile 128x128, BK=32, 8 warps (2x4, 64x32 each), 3-stage cp.async.
// Per 256-wide k-block: temp += XH*WQ + XL*WQ (MMA), then final += temp*s[n,kb].

#define BM 128
#define BN 128
#define BK 32
#define THREADS 256
#define TILE_B (BM * 64)          // 8 KB per fp16 [128][32] tile
#define STAGE_B (3 * TILE_B)      // XH, XL, WQ = 24 KB
#define NSTAGE 3
#define SMEM_B (NSTAGE * STAGE_B) // 72 KB

__global__ __launch_bounds__(THREADS, 1)
void gemm_hmma(float* __restrict__ C, int M, int N, int K) {
    extern __shared__ char sm[];
    const u32 sb = smem_u32(sm);
    const int tid = threadIdx.x;
    const int wid = tid >> 5;
    const int lane = tid & 31;
    const int m0 = blockIdx.x * BM;
    const int n0 = blockIdx.y * BN;
    const int warp_m = wid >> 2;      // 0..1
    const int warp_n = wid & 3;       // 0..3

    const size_t baseX = (size_t)m0 * K;
    const size_t baseW = (size_t)n0 * K;

    // cp.async mapping: 2 rows per thread per tile
    const int r0i = tid >> 2;
    const int kc0 = tid & 3;

    // ldmatrix lane decode
    const int matA = lane >> 3;
    const int rowA_base = warp_m * 64 + ((matA & 1) << 3) + (lane & 7);
    const int cA_sel = matA >> 1;
    const int matB = (lane >> 3) & 1;
    const int rowB_base = warp_n * 32 + (lane & 7);

    // scale columns handled by this thread: ec + nj*8, pairs (ec, ec+1)
    const int ecl = warp_n * 32 + (lane & 3) * 2;

    float fin[4][4][4];
    float tmp[4][4][4];
#pragma unroll
    for (int i = 0; i < 4; i++)
#pragma unroll
        for (int j = 0; j < 4; j++)
#pragma unroll
            for (int e = 0; e < 4; e++) fin[i][j][e] = 0.0f;

    const int NK = K / BK;   // 64; 8 iters per 256-wide scale block

    // ---- prefetch stages 0,1 ----
#pragma unroll
    for (int ps = 0; ps < 2; ps++) {
        const int k0 = ps * BK;
        const u32 st = sb + ps * STAGE_B;
#pragma unroll
        for (int t = 0; t < 2; t++) {
            int row = r0i + t * 64;
            u32 d = st + swz(row, kc0);
            size_t gx = baseX + (size_t)row * K + k0 + kc0 * 8;
            size_t gw = baseW + (size_t)row * K + k0 + kc0 * 8;
            cp16(d, g_XH + gx);
            cp16(d + TILE_B, g_XL + gx);
            cp16(d + 2 * TILE_B, g_WQ + gw);
        }
        cp_commit();
    }

    float2 s2[4];

    for (int kt = 0; kt < NK; kt++) {
        const int s = kt % NSTAGE;

        // prefetch stage kt+2
        if (kt + 2 < NK) {
            const int k0 = (kt + 2) * BK;
            const u32 st = sb + ((kt + 2) % NSTAGE) * STAGE_B;
#pragma unroll
            for (int t = 0; t < 2; t++) {
                int row = r0i + t * 64;
                u32 d = st + swz(row, kc0);
                size_t gx = baseX + (size_t)row * K + k0 + kc0 * 8;
                size_t gw = baseW + (size_t)row * K + k0 + kc0 * 8;
                cp16(d, g_XH + gx);
                cp16(d + TILE_B, g_XL + gx);
                cp16(d + 2 * TILE_B, g_WQ + gw);
            }
        }
        cp_commit();
        cp_wait2();
        __syncthreads();

        // ---- scale-block bookkeeping ----
        if ((kt & 7) == 0) {
            const int kb = kt >> 3;
            const float* sp = g_S + (size_t)kb * N + n0 + ecl;
#pragma unroll
            for (int nj = 0; nj < 4; nj++)
                s2[nj] = *(const float2*)(sp + nj * 8);
#pragma unroll
            for (int i = 0; i < 4; i++)
#pragma unroll
                for (int j = 0; j < 4; j++)
#pragma unroll
                    for (int e = 0; e < 4; e++) tmp[i][j][e] = 0.0f;
        }

        // ---- compute on stage s ----
        const u32 stAH = sb + s * STAGE_B;
        const u32 stAL = stAH + TILE_B;
        const u32 stBQ = stAH + 2 * TILE_B;

#pragma unroll
        for (int ks = 0; ks < 2; ks++) {
            u32 bq[4][2];
#pragma unroll
            for (int nj = 0; nj < 4; nj++) {
                u32 off = swz(rowB_base + nj * 8, ks * 2 + matB);
                ldsm2(stBQ + off, bq[nj][0], bq[nj][1]);
            }
#pragma unroll
            for (int mi = 0; mi < 4; mi++) {
                u32 off = swz(rowA_base + mi * 16, ks * 2 + cA_sel);
                u32 ah0, ah1, ah2, ah3, al0, al1, al2, al3;
                ldsm4(stAH + off, ah0, ah1, ah2, ah3);
                ldsm4(stAL + off, al0, al1, al2, al3);
#pragma unroll
                for (int nj = 0; nj < 4; nj++) {
                    mma16816(tmp[mi][nj], ah0, ah1, ah2, ah3, bq[nj][0], bq[nj][1]);
                    mma16816(tmp[mi][nj], al0, al1, al2, al3, bq[nj][0], bq[nj][1]);
                }
            }
        }

        // ---- end of 256-wide block: apply per-(n,kb) scale ----
        if ((kt & 7) == 7) {
#pragma unroll
            for (int mi = 0; mi < 4; mi++)
#pragma unroll
                for (int nj = 0; nj < 4; nj++) {
                    fin[mi][nj][0] = fmaf(tmp[mi][nj][0], s2[nj].x, fin[mi][nj][0]);
                    fin[mi][nj][1] = fmaf(tmp[mi][nj][1], s2[nj].y, fin[mi][nj][1]);
                    fin[mi][nj][2] = fmaf(tmp[mi][nj][2], s2[nj].x, fin[mi][nj][2]);
                    fin[mi][nj][3] = fmaf(tmp[mi][nj][3], s2[nj].y, fin[mi][nj][3]);
                }
        }
        __syncthreads();
    }

    // ---- epilogue ----
    const int er = m0 + warp_m * 64 + (lane >> 2);
    const int ec = n0 + ecl;
#pragma unroll
    for (int mi = 0; mi < 4; mi++) {
#pragma unroll
        for (int nj = 0; nj < 4; nj++) {
            float* p0 = C + (size_t)(er + mi * 16) * N + ec + nj * 8;
            float* p1 = C + (size_t)(er + mi * 16 + 8) * N + ec + nj * 8;
            *(float2*)p0 = make_float2(fin[mi][nj][0], fin[mi][nj][1]);
            *(float2*)p1 = make_float2(fin[mi][nj][2], fin[mi][nj][3]);
        }
    }
}

// ---------------- launch ----------------

extern "C" void kernel_launch(void* const* d_in, const int* in_sizes, int n_in,
                              void* d_out, int out_size) {
    const float* X  = (const float*)d_in[0];   // [M, K] fp32
    const int*   Q  = (const int*)d_in[1];     // [N, K] int32 codes
    const float* AM = (const float*)d_in[2];   // [N, K/256] fp32

    double s0 = (double)in_sizes[0];
    double s1 = (double)in_sizes[1];
    double so = (double)out_size;
    int K = (int)(sqrt(s0 * s1 / so) + 0.5);
    int M = (int)(s0 / K + 0.5);
    int N = (int)(s1 / K + 0.5);
    int nblk = K >> 8;

    int xt4 = (M * K) / 4;
    split_x_kernel<<<(xt4 + 255) / 256, 256>>>(X, xt4);
    int wt8 = (int)(((long long)N * K) / 8);
    prep_w_kernel<<<(wt8 + 255) / 256, 256>>>(Q, wt8);
    int st = N * nblk;
    prep_s_kernel<<<(st + 255) / 256, 256>>>(AM, N, nblk);

    cudaFuncSetAttribute(gemm_hmma, cudaFuncAttributeMaxDynamicSharedMemorySize, SMEM_B);
    dim3 grid(M / BM, N / BN);   // m fastest: W n-stripe shared via L2 within a wave
    gemm_hmma<<<grid, THREADS, SMEM_B>>>((float*)d_out, M, N, K);
}

// round 7
// speedup vs baseline: 4.1673x; 1.1726x over previous
#include <cuda_runtime.h>
#include <cuda_fp16.h>
#include <math.h>
#include <stdint.h>

typedef unsigned int u32;

// Fixed dataset shapes: M=4096, K=2048, N=32000
#define MAX_M 4096
#define MAX_K 2048
#define MAX_V 32000
#define MAX_NBLK (MAX_K / 256)

// Static device scratch (allocation-free rule)
__device__ __half g_XH[(size_t)MAX_M * MAX_K];
__device__ __half g_XL[(size_t)MAX_M * MAX_K];
__device__ __half g_WQ[(size_t)MAX_V * MAX_K];   // exact codes (q - 127.5) in fp16
__device__ float  g_S[(size_t)MAX_NBLK * MAX_V]; // transposed scales absmax/127.5

// ---------------- PTX helpers ----------------

static __device__ __forceinline__ u32 smem_u32(const void* p) {
    u32 a;
    asm("{ .reg .u64 t; cvta.to.shared.u64 t, %1; cvt.u32.u64 %0, t; }"
        : "=r"(a) : "l"(p));
    return a;
}

static __device__ __forceinline__ void cp16(u32 d, const void* g) {
    asm volatile("cp.async.cg.shared.global [%0], [%1], 16;"
                 :: "r"(d), "l"(g) : "memory");
}
static __device__ __forceinline__ void cp_commit() {
    asm volatile("cp.async.commit_group;" ::: "memory");
}
static __device__ __forceinline__ void cp_wait2() {
    asm volatile("cp.async.wait_group 2;" ::: "memory");
}

static __device__ __forceinline__ void ldsm4(u32 a, u32& r0, u32& r1, u32& r2, u32& r3) {
    asm volatile("ldmatrix.sync.aligned.m8n8.x4.shared.b16 {%0,%1,%2,%3}, [%4];"
                 : "=r"(r0), "=r"(r1), "=r"(r2), "=r"(r3) : "r"(a));
}
static __device__ __forceinline__ void ldsm2(u32 a, u32& r0, u32& r1) {
    asm volatile("ldmatrix.sync.aligned.m8n8.x2.shared.b16 {%0,%1}, [%2];"
                 : "=r"(r0), "=r"(r1) : "r"(a));
}

static __device__ __forceinline__ void mma16816(float* c,
                                                u32 a0, u32 a1, u32 a2, u32 a3,
                                                u32 b0, u32 b1) {
    asm volatile(
        "mma.sync.aligned.m16n8k16.row.col.f32.f16.f16.f32 "
        "{%0,%1,%2,%3}, {%4,%5,%6,%7}, {%8,%9}, {%0,%1,%2,%3};"
        : "+f"(c[0]), "+f"(c[1]), "+f"(c[2]), "+f"(c[3])
        : "r"(a0), "r"(a1), "r"(a2), "r"(a3), "r"(b0), "r"(b1));
}

// XOR swizzle for 64B rows (BK=32 f16): conflict-free STS.128 + ldmatrix.
static __device__ __forceinline__ u32 swz(int row, int chunk) {
    return (u32)(row * 64 + ((chunk ^ ((row >> 1) & 3)) << 4));
}

// ---------------- Pre-pass kernels ----------------

__global__ void split_x_kernel(const float* __restrict__ X, int total4) {
    int i = blockIdx.x * 256 + threadIdx.x;
    if (i >= total4) return;
    float4 v = ((const float4*)X)[i];
    float f[4] = {v.x, v.y, v.z, v.w};
    __half h[4], l[4];
#pragma unroll
    for (int j = 0; j < 4; j++) {
        h[j] = __float2half_rn(f[j]);
        l[j] = __float2half_rn(f[j] - __half2float(h[j]));
    }
    ((uint2*)g_XH)[i] = *(uint2*)h;
    ((uint2*)g_XL)[i] = *(uint2*)l;
}

__global__ void prep_w_kernel(const int* __restrict__ Q, int total8) {
    int i = blockIdx.x * 256 + threadIdx.x;
    if (i >= total8) return;
    int4 a = ((const int4*)Q)[2 * i];
    int4 b = ((const int4*)Q)[2 * i + 1];
    __half h[8];
    h[0] = __float2half_rn((float)a.x - 127.5f);
    h[1] = __float2half_rn((float)a.y - 127.5f);
    h[2] = __float2half_rn((float)a.z - 127.5f);
    h[3] = __float2half_rn((float)a.w - 127.5f);
    h[4] = __float2half_rn((float)b.x - 127.5f);
    h[5] = __float2half_rn((float)b.y - 127.5f);
    h[6] = __float2half_rn((float)b.z - 127.5f);
    h[7] = __float2half_rn((float)b.w - 127.5f);
    ((uint4*)g_WQ)[i] = *(uint4*)h;
}

__global__ void prep_s_kernel(const float* __restrict__ AM, int N, int nblk) {
    int i = blockIdx.x * 256 + threadIdx.x;
    if (i >= N * nblk) return;
    int kb = i / N;
    int n = i - kb * N;
    g_S[i] = AM[(size_t)n * nblk + kb] * (1.0f / 127.5f);
}

// ---------------- Main GEMM ----------------
// C[M,N] = X * W^T, exact-W codes + split-X (2 MMA terms), per-(n,kblock)
// scale applied on fp32 temp accumulator every 8 k-iters.
// CTA tile 64x128, 8 warps (2m x 4n, 32x32 each), 4-stage cp.async,
// ONE __syncthreads per k-iter, 2 CTAs/SM.

#define BM 64
#define BN 128
#define BK 32
#define THREADS 256
#define TILE_XB (BM * 64)          // 4 KB per X fp16 [64][32] tile
#define TILE_WB (BN * 64)          // 8 KB for W [128][32]
#define STAGE_B (2 * TILE_XB + TILE_WB)   // 16 KB: XH, XL, WQ
#define NSTAGE 4
#define SMEM_B (NSTAGE * STAGE_B)  // 64 KB

__global__ __launch_bounds__(THREADS, 2)
void gemm_hmma(float* __restrict__ C, int M, int N, int K) {
    extern __shared__ char sm[];
    const u32 sb = smem_u32(sm);
    const int tid = threadIdx.x;
    const int wid = tid >> 5;
    const int lane = tid & 31;
    const int m0 = blockIdx.x * BM;
    const int n0 = blockIdx.y * BN;
    const int warp_m = wid >> 2;      // 0..1
    const int warp_n = wid & 3;       // 0..3

    const size_t baseX = (size_t)m0 * K;
    const size_t baseW = (size_t)n0 * K;

    // cp.async mapping: 256 threads, 4 chunks each per stage
    // rows: XH r, XL r (r=tid>>2, 0..63), WQ r and r+64
    const int r0i = tid >> 2;
    const int kc0 = tid & 3;

    // ldmatrix lane decode
    const int matA = lane >> 3;
    const int rowA_base = warp_m * 32 + ((matA & 1) << 3) + (lane & 7);
    const int cA_sel = matA >> 1;
    const int matB = (lane >> 3) & 1;
    const int rowB_base = warp_n * 32 + (lane & 7);

    const int ecl = warp_n * 32 + (lane & 3) * 2;

    float fin[2][4][4];
    float tmp[2][4][4];
#pragma unroll
    for (int i = 0; i < 2; i++)
#pragma unroll
        for (int j = 0; j < 4; j++)
#pragma unroll
            for (int e = 0; e < 4; e++) fin[i][j][e] = 0.0f;

    const int NK = K / BK;   // 64

    // ---- prologue: prefetch stages 0..2 ----
#pragma unroll
    for (int ps = 0; ps < NSTAGE - 1; ps++) {
        const int k0 = ps * BK;
        const u32 st = sb + ps * STAGE_B;
        size_t gx = baseX + (size_t)r0i * K + k0 + kc0 * 8;
        u32 dx = st + swz(r0i, kc0);
        cp16(dx, g_XH + gx);
        cp16(dx + TILE_XB, g_XL + gx);
        size_t gw0 = baseW + (size_t)r0i * K + k0 + kc0 * 8;
        size_t gw1 = baseW + (size_t)(r0i + 64) * K + k0 + kc0 * 8;
        cp16(st + 2 * TILE_XB + swz(r0i, kc0), g_WQ + gw0);
        cp16(st + 2 * TILE_XB + swz(r0i + 64, kc0), g_WQ + gw1);
        cp_commit();
    }

    float2 s2[4];

    for (int kt = 0; kt < NK; kt++) {
        const int s = kt & (NSTAGE - 1);

        cp_wait2();           // oldest group (stage kt) landed
        __syncthreads();      // all warps: stage kt visible, stage kt-1 reads done

        // ---- prefetch stage kt+3 into buffer (kt-1)%4 (now safe) ----
        if (kt + NSTAGE - 1 < NK) {
            const int k0 = (kt + NSTAGE - 1) * BK;
            const u32 st = sb + ((kt + NSTAGE - 1) & (NSTAGE - 1)) * STAGE_B;
            size_t gx = baseX + (size_t)r0i * K + k0 + kc0 * 8;
            u32 dx = st + swz(r0i, kc0);
            cp16(dx, g_XH + gx);
            cp16(dx + TILE_XB, g_XL + gx);
            size_t gw0 = baseW + (size_t)r0i * K + k0 + kc0 * 8;
            size_t gw1 = baseW + (size_t)(r0i + 64) * K + k0 + kc0 * 8;
            cp16(st + 2 * TILE_XB + swz(r0i, kc0), g_WQ + gw0);
            cp16(st + 2 * TILE_XB + swz(r0i + 64, kc0), g_WQ + gw1);
        }
        cp_commit();          // unconditional: keeps group accounting uniform

        // ---- scale-block bookkeeping (every 8 iters = 256 k) ----
        if ((kt & 7) == 0) {
            const int kb = kt >> 3;
            const float* sp = g_S + (size_t)kb * N + n0 + ecl;
#pragma unroll
            for (int nj = 0; nj < 4; nj++)
                s2[nj] = *(const float2*)(sp + nj * 8);
#pragma unroll
            for (int i = 0; i < 2; i++)
#pragma unroll
                for (int j = 0; j < 4; j++)
#pragma unroll
                    for (int e = 0; e < 4; e++) tmp[i][j][e] = 0.0f;
        }

        // ---- compute stage s ----
        const u32 stAH = sb + s * STAGE_B;
        const u32 stAL = stAH + TILE_XB;
        const u32 stBQ = stAH + 2 * TILE_XB;

#pragma unroll
        for (int ks = 0; ks < 2; ks++) {
            u32 bq[4][2];
#pragma unroll
            for (int nj = 0; nj < 4; nj++) {
                u32 off = swz(rowB_base + nj * 8, ks * 2 + matB);
                ldsm2(stBQ + off, bq[nj][0], bq[nj][1]);
            }
#pragma unroll
            for (int mi = 0; mi < 2; mi++) {
                u32 off = swz(rowA_base + mi * 16, ks * 2 + cA_sel);
                u32 ah0, ah1, ah2, ah3, al0, al1, al2, al3;
                ldsm4(stAH + off, ah0, ah1, ah2, ah3);
                ldsm4(stAL + off, al0, al1, al2, al3);
#pragma unroll
                for (int nj = 0; nj < 4; nj++) {
                    mma16816(tmp[mi][nj], ah0, ah1, ah2, ah3, bq[nj][0], bq[nj][1]);
                    mma16816(tmp[mi][nj], al0, al1, al2, al3, bq[nj][0], bq[nj][1]);
                }
            }
        }

        // ---- end of 256-wide block: apply per-(n,kb) scale ----
        if ((kt & 7) == 7) {
#pragma unroll
            for (int mi = 0; mi < 2; mi++)
#pragma unroll
                for (int nj = 0; nj < 4; nj++) {
                    fin[mi][nj][0] = fmaf(tmp[mi][nj][0], s2[nj].x, fin[mi][nj][0]);
                    fin[mi][nj][1] = fmaf(tmp[mi][nj][1], s2[nj].y, fin[mi][nj][1]);
                    fin[mi][nj][2] = fmaf(tmp[mi][nj][2], s2[nj].x, fin[mi][nj][2]);
                    fin[mi][nj][3] = fmaf(tmp[mi][nj][3], s2[nj].y, fin[mi][nj][3]);
                }
        }
    }

    // ---- epilogue ----
    const int er = m0 + warp_m * 32 + (lane >> 2);
    const int ec = n0 + ecl;
#pragma unroll
    for (int mi = 0; mi < 2; mi++) {
#pragma unroll
        for (int nj = 0; nj < 4; nj++) {
            float* p0 = C + (size_t)(er + mi * 16) * N + ec + nj * 8;
            float* p1 = C + (size_t)(er + mi * 16 + 8) * N + ec + nj * 8;
            *(float2*)p0 = make_float2(fin[mi][nj][0], fin[mi][nj][1]);
            *(float2*)p1 = make_float2(fin[mi][nj][2], fin[mi][nj][3]);
        }
    }
}

// ---------------- launch ----------------

extern "C" void kernel_launch(void* const* d_in, const int* in_sizes, int n_in,
                              void* d_out, int out_size) {
    const float* X  = (const float*)d_in[0];
    const int*   Q  = (const int*)d_in[1];
    const float* AM = (const float*)d_in[2];

    double s0 = (double)in_sizes[0];
    double s1 = (double)in_sizes[1];
    double so = (double)out_size;
    int K = (int)(sqrt(s0 * s1 / so) + 0.5);
    int M = (int)(s0 / K + 0.5);
    int N = (int)(s1 / K + 0.5);
    int nblk = K >> 8;

    int xt4 = (M * K) / 4;
    split_x_kernel<<<(xt4 + 255) / 256, 256>>>(X, xt4);
    int wt8 = (int)(((long long)N * K) / 8);
    prep_w_kernel<<<(wt8 + 255) / 256, 256>>>(Q, wt8);
    int st = N * nblk;
    prep_s_kernel<<<(st + 255) / 256, 256>>>(AM, N, nblk);

    cudaFuncSetAttribute(gemm_hmma, cudaFuncAttributeMaxDynamicSharedMemorySize, SMEM_B);
    dim3 grid(M / BM, N / BN);   // m fastest: W n-stripe shared via L2 within a wave
    gemm_hmma<<<grid, THREADS, SMEM_B>>>((float*)d_out, M, N, K);
}

// round 8
// speedup vs baseline: 4.6058x; 1.1052x over previous
#include <cuda_runtime.h>
#include <cuda_fp16.h>
#include <math.h>
#include <stdint.h>

typedef unsigned int u32;

// Fixed dataset shapes: M=4096, K=2048, N=32000
#define MAX_M 4096
#define MAX_K 2048
#define MAX_V 32000
#define MAX_NBLK (MAX_K / 256)

// Static device scratch (allocation-free rule)
__device__ __half g_XH[(size_t)MAX_M * MAX_K];
__device__ __half g_XL[(size_t)MAX_M * MAX_K];
__device__ __half g_WQ[(size_t)MAX_V * MAX_K];   // exact codes (q - 127.5) in fp16
__device__ float  g_S[(size_t)MAX_NBLK * MAX_V]; // transposed scales absmax/127.5

// ---------------- PTX helpers ----------------

static __device__ __forceinline__ u32 smem_u32(const void* p) {
    u32 a;
    asm("{ .reg .u64 t; cvta.to.shared.u64 t, %1; cvt.u32.u64 %0, t; }"
        : "=r"(a) : "l"(p));
    return a;
}

static __device__ __forceinline__ void cp16(u32 d, const void* g) {
    asm volatile("cp.async.cg.shared.global [%0], [%1], 16;"
                 :: "r"(d), "l"(g) : "memory");
}
static __device__ __forceinline__ void cp_commit() {
    asm volatile("cp.async.commit_group;" ::: "memory");
}
static __device__ __forceinline__ void cp_wait1() {
    asm volatile("cp.async.wait_group 1;" ::: "memory");
}

static __device__ __forceinline__ void ldsm4(u32 a, u32& r0, u32& r1, u32& r2, u32& r3) {
    asm volatile("ldmatrix.sync.aligned.m8n8.x4.shared.b16 {%0,%1,%2,%3}, [%4];"
                 : "=r"(r0), "=r"(r1), "=r"(r2), "=r"(r3) : "r"(a));
}
static __device__ __forceinline__ void ldsm2(u32 a, u32& r0, u32& r1) {
    asm volatile("ldmatrix.sync.aligned.m8n8.x2.shared.b16 {%0,%1}, [%2];"
                 : "=r"(r0), "=r"(r1) : "r"(a));
}

static __device__ __forceinline__ void mma16816(float* c,
                                                u32 a0, u32 a1, u32 a2, u32 a3,
                                                u32 b0, u32 b1) {
    asm volatile(
        "mma.sync.aligned.m16n8k16.row.col.f32.f16.f16.f32 "
        "{%0,%1,%2,%3}, {%4,%5,%6,%7}, {%8,%9}, {%0,%1,%2,%3};"
        : "+f"(c[0]), "+f"(c[1]), "+f"(c[2]), "+f"(c[3])
        : "r"(a0), "r"(a1), "r"(a2), "r"(a3), "r"(b0), "r"(b1));
}

// Full SW128 swizzle for 128B rows (BK=64 f16): conflict-free STS.128 + ldmatrix.
static __device__ __forceinline__ u32 swz(int row, int chunk) {
    return (u32)(row * 128 + ((chunk ^ (row & 7)) << 4));
}

// ---------------- Pre-pass kernels ----------------

__global__ void split_x_kernel(const float* __restrict__ X, int total4) {
    int i = blockIdx.x * 256 + threadIdx.x;
    if (i >= total4) return;
    float4 v = ((const float4*)X)[i];
    float f[4] = {v.x, v.y, v.z, v.w};
    __half h[4], l[4];
#pragma unroll
    for (int j = 0; j < 4; j++) {
        h[j] = __float2half_rn(f[j]);
        l[j] = __float2half_rn(f[j] - __half2float(h[j]));
    }
    ((uint2*)g_XH)[i] = *(uint2*)h;
    ((uint2*)g_XL)[i] = *(uint2*)l;
}

__global__ void prep_w_kernel(const int* __restrict__ Q, int total8) {
    int i = blockIdx.x * 256 + threadIdx.x;
    if (i >= total8) return;
    int4 a = ((const int4*)Q)[2 * i];
    int4 b = ((const int4*)Q)[2 * i + 1];
    __half h[8];
    h[0] = __float2half_rn((float)a.x - 127.5f);
    h[1] = __float2half_rn((float)a.y - 127.5f);
    h[2] = __float2half_rn((float)a.z - 127.5f);
    h[3] = __float2half_rn((float)a.w - 127.5f);
    h[4] = __float2half_rn((float)b.x - 127.5f);
    h[5] = __float2half_rn((float)b.y - 127.5f);
    h[6] = __float2half_rn((float)b.z - 127.5f);
    h[7] = __float2half_rn((float)b.w - 127.5f);
    ((uint4*)g_WQ)[i] = *(uint4*)h;
}

__global__ void prep_s_kernel(const float* __restrict__ AM, int N, int nblk) {
    int i = blockIdx.x * 256 + threadIdx.x;
    if (i >= N * nblk) return;
    int kb = i / N;
    int n = i - kb * N;
    g_S[i] = AM[(size_t)n * nblk + kb] * (1.0f / 127.5f);
}

// ---------------- Main GEMM ----------------
// C[M,N] = X * W^T, exact-W fp16 codes + split-X (2 MMA terms).
// CTA tile 64x128, BK=64, 8 warps (2m x 4n, 32x32), 3-stage cp.async,
// ONE __syncthreads per BK=64 (32 total), 2 CTAs/SM.

#define BM 64
#define BN 128
#define BK 64
#define THREADS 256
#define TILE_XB (BM * 128)         // 8 KB per X fp16 [64][64] tile
#define TILE_WB (BN * 128)         // 16 KB for W [128][64]
#define STAGE_B (2 * TILE_XB + TILE_WB)   // 32 KB
#define NSTAGE 3
#define SMEM_B (NSTAGE * STAGE_B)  // 96 KB

__global__ __launch_bounds__(THREADS, 2)
void gemm_hmma(float* __restrict__ C, int M, int N, int K) {
    extern __shared__ char sm[];
    const u32 sb = smem_u32(sm);
    const int tid = threadIdx.x;
    const int wid = tid >> 5;
    const int lane = tid & 31;
    const int m0 = blockIdx.x * BM;
    const int n0 = blockIdx.y * BN;
    const int warp_m = wid >> 2;      // 0..1
    const int warp_n = wid & 3;       // 0..3

    const size_t baseX = (size_t)m0 * K;
    const size_t baseW = (size_t)n0 * K;

    // cp.async mapping: 8 threads per 128B row
    const int lrow = tid >> 3;        // 0..31
    const int lchk = tid & 7;         // 0..7

    // ldmatrix lane decode
    const int matA = lane >> 3;
    const int rowA_base = warp_m * 32 + ((matA & 1) << 3) + (lane & 7);
    const int cA_sel = matA >> 1;
    const int matB = (lane >> 3) & 1;
    const int rowB_base = warp_n * 32 + (lane & 7);

    const int ecl = warp_n * 32 + (lane & 3) * 2;

    float fin[2][4][4];
    float tmp[2][4][4];
#pragma unroll
    for (int i = 0; i < 2; i++)
#pragma unroll
        for (int j = 0; j < 4; j++)
#pragma unroll
            for (int e = 0; e < 4; e++) fin[i][j][e] = 0.0f;

    const int NK = K / BK;   // 32

    // ---- prologue: prefetch stages 0,1 ----
#pragma unroll
    for (int ps = 0; ps < NSTAGE - 1; ps++) {
        const int k0 = ps * BK;
        const u32 st = sb + ps * STAGE_B;
#pragma unroll
        for (int t = 0; t < 2; t++) {   // X tiles: 64 rows
            int row = lrow + t * 32;
            u32 sw = swz(row, lchk);
            size_t gx = baseX + (size_t)row * K + k0 + lchk * 8;
            cp16(st + sw, g_XH + gx);
            cp16(st + TILE_XB + sw, g_XL + gx);
        }
#pragma unroll
        for (int t = 0; t < 4; t++) {   // W tile: 128 rows
            int row = lrow + t * 32;
            u32 sw = swz(row, lchk);
            size_t gw = baseW + (size_t)row * K + k0 + lchk * 8;
            cp16(st + 2 * TILE_XB + sw, g_WQ + gw);
        }
        cp_commit();
    }

    float2 s2[4];

    for (int kt = 0; kt < NK; kt++) {
        const int s = kt % NSTAGE;

        cp_wait1();           // stage kt landed (in-order group completion)
        __syncthreads();      // stage kt visible; stage kt-1 reads complete

        // ---- prefetch stage kt+2 into buffer (kt-1)%3 (now safe) ----
        if (kt + NSTAGE - 1 < NK) {
            const int k0 = (kt + NSTAGE - 1) * BK;
            const u32 st = sb + ((kt + NSTAGE - 1) % NSTAGE) * STAGE_B;
#pragma unroll
            for (int t = 0; t < 2; t++) {
                int row = lrow + t * 32;
                u32 sw = swz(row, lchk);
                size_t gx = baseX + (size_t)row * K + k0 + lchk * 8;
                cp16(st + sw, g_XH + gx);
                cp16(st + TILE_XB + sw, g_XL + gx);
            }
#pragma unroll
            for (int t = 0; t < 4; t++) {
                int row = lrow + t * 32;
                u32 sw = swz(row, lchk);
                size_t gw = baseW + (size_t)row * K + k0 + lchk * 8;
                cp16(st + 2 * TILE_XB + sw, g_WQ + gw);
            }
        }
        cp_commit();          // unconditional: uniform group accounting

        // ---- scale-block bookkeeping (256 k = 4 iters) ----
        if ((kt & 3) == 0) {
            const int kb = kt >> 2;
            const float* sp = g_S + (size_t)kb * N + n0 + ecl;
#pragma unroll
            for (int nj = 0; nj < 4; nj++)
                s2[nj] = *(const float2*)(sp + nj * 8);
#pragma unroll
            for (int i = 0; i < 2; i++)
#pragma unroll
                for (int j = 0; j < 4; j++)
#pragma unroll
                    for (int e = 0; e < 4; e++) tmp[i][j][e] = 0.0f;
        }

        // ---- compute stage s: 4 k16 sub-steps ----
        const u32 stAH = sb + s * STAGE_B;
        const u32 stAL = stAH + TILE_XB;
        const u32 stBQ = stAH + 2 * TILE_XB;

#pragma unroll
        for (int ks = 0; ks < 4; ks++) {
            u32 bq[4][2];
#pragma unroll
            for (int nj = 0; nj < 4; nj++) {
                u32 off = swz(rowB_base + nj * 8, ks * 2 + matB);
                ldsm2(stBQ + off, bq[nj][0], bq[nj][1]);
            }
#pragma unroll
            for (int mi = 0; mi < 2; mi++) {
                u32 off = swz(rowA_base + mi * 16, ks * 2 + cA_sel);
                u32 ah0, ah1, ah2, ah3, al0, al1, al2, al3;
                ldsm4(stAH + off, ah0, ah1, ah2, ah3);
                ldsm4(stAL + off, al0, al1, al2, al3);
#pragma unroll
                for (int nj = 0; nj < 4; nj++) {
                    mma16816(tmp[mi][nj], ah0, ah1, ah2, ah3, bq[nj][0], bq[nj][1]);
                    mma16816(tmp[mi][nj], al0, al1, al2, al3, bq[nj][0], bq[nj][1]);
                }
            }
        }

        // ---- end of 256-wide block: apply per-(n,kb) scale ----
        if ((kt & 3) == 3) {
#pragma unroll
            for (int mi = 0; mi < 2; mi++)
#pragma unroll
                for (int nj = 0; nj < 4; nj++) {
                    fin[mi][nj][0] = fmaf(tmp[mi][nj][0], s2[nj].x, fin[mi][nj][0]);
                    fin[mi][nj][1] = fmaf(tmp[mi][nj][1], s2[nj].y, fin[mi][nj][1]);
                    fin[mi][nj][2] = fmaf(tmp[mi][nj][2], s2[nj].x, fin[mi][nj][2]);
                    fin[mi][nj][3] = fmaf(tmp[mi][nj][3], s2[nj].y, fin[mi][nj][3]);
                }
        }
    }

    // ---- epilogue ----
    const int er = m0 + warp_m * 32 + (lane >> 2);
    const int ec = n0 + ecl;
#pragma unroll
    for (int mi = 0; mi < 2; mi++) {
#pragma unroll
        for (int nj = 0; nj < 4; nj++) {
            float* p0 = C + (size_t)(er + mi * 16) * N + ec + nj * 8;
            float* p1 = C + (size_t)(er + mi * 16 + 8) * N + ec + nj * 8;
            *(float2*)p0 = make_float2(fin[mi][nj][0], fin[mi][nj][1]);
            *(float2*)p1 = make_float2(fin[mi][nj][2], fin[mi][nj][3]);
        }
    }
}

// ---------------- launch ----------------

extern "C" void kernel_launch(void* const* d_in, const int* in_sizes, int n_in,
                              void* d_out, int out_size) {
    const float* X  = (const float*)d_in[0];
    const int*   Q  = (const int*)d_in[1];
    const float* AM = (const float*)d_in[2];

    double s0 = (double)in_sizes[0];
    double s1 = (double)in_sizes[1];
    double so = (double)out_size;
    int K = (int)(sqrt(s0 * s1 / so) + 0.5);
    int M = (int)(s0 / K + 0.5);
    int N = (int)(s1 / K + 0.5);
    int nblk = K >> 8;

    int xt4 = (M * K) / 4;
    split_x_kernel<<<(xt4 + 255) / 256, 256>>>(X, xt4);
    int wt8 = (int)(((long long)N * K) / 8);
    prep_w_kernel<<<(wt8 + 255) / 256, 256>>>(Q, wt8);
    int st = N * nblk;
    prep_s_kernel<<<(st + 255) / 256, 256>>>(AM, N, nblk);

    cudaFuncSetAttribute(gemm_hmma, cudaFuncAttributeMaxDynamicSharedMemorySize, SMEM_B);
    dim3 grid(M / BM, N / BN);   // m fastest: W n-stripe shared via L2 within a wave
    gemm_hmma<<<grid, THREADS, SMEM_B>>>((float*)d_out, M, N, K);
}

// round 9
// speedup vs baseline: 7.1698x; 1.5567x over previous
#include <cuda_runtime.h>
#include <cuda_fp16.h>
#include <math.h>
#include <stdint.h>

typedef unsigned int u32;

// Fixed dataset shapes: M=4096, K=2048, N=32000
#define MAX_M 4096
#define MAX_K 2048
#define MAX_V 32000
#define MAX_NBLK (MAX_K / 256)

// Static device scratch (allocation-free rule)
__device__ __half g_XH[(size_t)MAX_M * MAX_K];   // x rounded to fp16
__device__ __half g_WQ[(size_t)MAX_V * MAX_K];   // exact codes (q - 127.5) in fp16
__device__ float  g_S[(size_t)MAX_NBLK * MAX_V]; // transposed scales absmax/127.5

// ---------------- PTX helpers ----------------

static __device__ __forceinline__ u32 smem_u32(const void* p) {
    u32 a;
    asm("{ .reg .u64 t; cvta.to.shared.u64 t, %1; cvt.u32.u64 %0, t; }"
        : "=r"(a) : "l"(p));
    return a;
}

static __device__ __forceinline__ void cp16(u32 d, const void* g) {
    asm volatile("cp.async.cg.shared.global [%0], [%1], 16;"
                 :: "r"(d), "l"(g) : "memory");
}
static __device__ __forceinline__ void cp_commit() {
    asm volatile("cp.async.commit_group;" ::: "memory");
}
static __device__ __forceinline__ void cp_wait2() {
    asm volatile("cp.async.wait_group 2;" ::: "memory");
}

static __device__ __forceinline__ void ldsm4(u32 a, u32& r0, u32& r1, u32& r2, u32& r3) {
    asm volatile("ldmatrix.sync.aligned.m8n8.x4.shared.b16 {%0,%1,%2,%3}, [%4];"
                 : "=r"(r0), "=r"(r1), "=r"(r2), "=r"(r3) : "r"(a));
}

static __device__ __forceinline__ void mma16816(float* c,
                                                u32 a0, u32 a1, u32 a2, u32 a3,
                                                u32 b0, u32 b1) {
    asm volatile(
        "mma.sync.aligned.m16n8k16.row.col.f32.f16.f16.f32 "
        "{%0,%1,%2,%3}, {%4,%5,%6,%7}, {%8,%9}, {%0,%1,%2,%3};"
        : "+f"(c[0]), "+f"(c[1]), "+f"(c[2]), "+f"(c[3])
        : "r"(a0), "r"(a1), "r"(a2), "r"(a3), "r"(b0), "r"(b1));
}

// Full SW128 swizzle for 128B rows (BK=64 f16): conflict-free STS.128 + ldmatrix.
static __device__ __forceinline__ u32 swz(int row, int chunk) {
    return (u32)(row * 128 + ((chunk ^ (row & 7)) << 4));
}

// ---------------- Pre-pass kernels ----------------

__global__ void prep_x_kernel(const float* __restrict__ X, int total4) {
    int i = blockIdx.x * 256 + threadIdx.x;
    if (i >= total4) return;
    float4 v = ((const float4*)X)[i];
    __half h[4];
    h[0] = __float2half_rn(v.x);
    h[1] = __float2half_rn(v.y);
    h[2] = __float2half_rn(v.z);
    h[3] = __float2half_rn(v.w);
    ((uint2*)g_XH)[i] = *(uint2*)h;
}

__global__ void prep_w_kernel(const int* __restrict__ Q, int total8) {
    int i = blockIdx.x * 256 + threadIdx.x;
    if (i >= total8) return;
    int4 a = ((const int4*)Q)[2 * i];
    int4 b = ((const int4*)Q)[2 * i + 1];
    __half h[8];
    h[0] = __float2half_rn((float)a.x - 127.5f);
    h[1] = __float2half_rn((float)a.y - 127.5f);
    h[2] = __float2half_rn((float)a.z - 127.5f);
    h[3] = __float2half_rn((float)a.w - 127.5f);
    h[4] = __float2half_rn((float)b.x - 127.5f);
    h[5] = __float2half_rn((float)b.y - 127.5f);
    h[6] = __float2half_rn((float)b.z - 127.5f);
    h[7] = __float2half_rn((float)b.w - 127.5f);
    ((uint4*)g_WQ)[i] = *(uint4*)h;
}

__global__ void prep_s_kernel(const float* __restrict__ AM, int N, int nblk) {
    int i = blockIdx.x * 256 + threadIdx.x;
    if (i >= N * nblk) return;
    int kb = i / N;
    int n = i - kb * N;
    g_S[i] = AM[(size_t)n * nblk + kb] * (1.0f / 127.5f);
}

// ---------------- Main GEMM ----------------
// C[M,N] = X(fp16) * Wcodes(fp16)^T with per-(n, 256-k-block) scale applied
// on an fp32 temp accumulator. CTA 64x128, BK=64, 8 warps (2m x 4n, 32x32),
// 4-stage cp.async, ONE __syncthreads per BK, 2 CTAs/SM.

#define BM 64
#define BN 128
#define BK 64
#define THREADS 256
#define TILE_XB (BM * 128)         // 8 KB X [64][64] f16
#define TILE_WB (BN * 128)         // 16 KB W [128][64] f16
#define STAGE_B (TILE_XB + TILE_WB)   // 24 KB
#define NSTAGE 4
#define SMEM_B (NSTAGE * STAGE_B)  // 96 KB

__global__ __launch_bounds__(THREADS, 2)
void gemm_hmma(float* __restrict__ C, int M, int N, int K) {
    extern __shared__ char sm[];
    const u32 sb = smem_u32(sm);
    const int tid = threadIdx.x;
    const int wid = tid >> 5;
    const int lane = tid & 31;
    const int m0 = blockIdx.x * BM;
    const int n0 = blockIdx.y * BN;
    const int warp_m = wid >> 2;      // 0..1
    const int warp_n = wid & 3;       // 0..3

    const size_t baseX = (size_t)m0 * K;
    const size_t baseW = (size_t)n0 * K;

    // cp.async mapping: 8 threads per 128B row
    const int lrow = tid >> 3;        // 0..31
    const int lchk = tid & 7;         // 0..7

    // A ldmatrix lane decode (x4: m16 x k16 per mi)
    const int matA = lane >> 3;
    const int rowA_base = warp_m * 32 + ((matA & 1) << 3) + (lane & 7);
    const int cA_sel = matA >> 1;
    // B ldmatrix lane decode (x4 covers 2 nj x 2 k-halves)
    const int matB = lane >> 3;                    // 0..3
    const int rowB_base = warp_n * 32 + ((matB >> 1) << 3) + (lane & 7);
    const int cB_sel = matB & 1;

    const int ecl = warp_n * 32 + (lane & 3) * 2;

    float fin[2][4][4];
    float tmp[2][4][4];
#pragma unroll
    for (int i = 0; i < 2; i++)
#pragma unroll
        for (int j = 0; j < 4; j++)
#pragma unroll
            for (int e = 0; e < 4; e++) fin[i][j][e] = 0.0f;

    const int NK = K / BK;   // 32

    // ---- prologue: prefetch stages 0..2 ----
#pragma unroll
    for (int ps = 0; ps < NSTAGE - 1; ps++) {
        const int k0 = ps * BK;
        const u32 st = sb + ps * STAGE_B;
#pragma unroll
        for (int t = 0; t < 2; t++) {   // X: 64 rows
            int row = lrow + t * 32;
            size_t gx = baseX + (size_t)row * K + k0 + lchk * 8;
            cp16(st + swz(row, lchk), g_XH + gx);
        }
#pragma unroll
        for (int t = 0; t < 4; t++) {   // W: 128 rows
            int row = lrow + t * 32;
            size_t gw = baseW + (size_t)row * K + k0 + lchk * 8;
            cp16(st + TILE_XB + swz(row, lchk), g_WQ + gw);
        }
        cp_commit();
    }

    float2 s2[4];

    for (int kt = 0; kt < NK; kt++) {
        const int s = kt & (NSTAGE - 1);

        cp_wait2();           // oldest group (stage kt) landed
        __syncthreads();      // stage kt visible; stage kt-1 reads complete

        // ---- prefetch stage kt+3 into buffer (kt-1)%4 (now safe) ----
        if (kt + NSTAGE - 1 < NK) {
            const int k0 = (kt + NSTAGE - 1) * BK;
            const u32 st = sb + ((kt + NSTAGE - 1) & (NSTAGE - 1)) * STAGE_B;
#pragma unroll
            for (int t = 0; t < 2; t++) {
                int row = lrow + t * 32;
                size_t gx = baseX + (size_t)row * K + k0 + lchk * 8;
                cp16(st + swz(row, lchk), g_XH + gx);
            }
#pragma unroll
            for (int t = 0; t < 4; t++) {
                int row = lrow + t * 32;
                size_t gw = baseW + (size_t)row * K + k0 + lchk * 8;
                cp16(st + TILE_XB + swz(row, lchk), g_WQ + gw);
            }
        }
        cp_commit();          // unconditional: uniform group accounting

        // ---- scale-block bookkeeping (256 k = 4 iters) ----
        if ((kt & 3) == 0) {
            const int kb = kt >> 2;
            const float* sp = g_S + (size_t)kb * N + n0 + ecl;
#pragma unroll
            for (int nj = 0; nj < 4; nj++)
                s2[nj] = *(const float2*)(sp + nj * 8);
#pragma unroll
            for (int i = 0; i < 2; i++)
#pragma unroll
                for (int j = 0; j < 4; j++)
#pragma unroll
                    for (int e = 0; e < 4; e++) tmp[i][j][e] = 0.0f;
        }

        // ---- compute stage s: 4 k16 sub-steps ----
        const u32 stA = sb + s * STAGE_B;
        const u32 stB = stA + TILE_XB;

#pragma unroll
        for (int ks = 0; ks < 4; ks++) {
            // B frags: one ldsm4 covers 2 nj x 2 k-halves
            u32 bq[4][2];
#pragma unroll
            for (int njp = 0; njp < 2; njp++) {
                u32 off = swz(rowB_base + njp * 16, ks * 2 + cB_sel);
                ldsm4(stB + off, bq[njp * 2][0], bq[njp * 2][1],
                      bq[njp * 2 + 1][0], bq[njp * 2 + 1][1]);
            }
#pragma unroll
            for (int mi = 0; mi < 2; mi++) {
                u32 off = swz(rowA_base + mi * 16, ks * 2 + cA_sel);
                u32 a0, a1, a2, a3;
                ldsm4(stA + off, a0, a1, a2, a3);
#pragma unroll
                for (int nj = 0; nj < 4; nj++)
                    mma16816(tmp[mi][nj], a0, a1, a2, a3, bq[nj][0], bq[nj][1]);
            }
        }

        // ---- end of 256-wide block: apply per-(n,kb) scale ----
        if ((kt & 3) == 3) {
#pragma unroll
            for (int mi = 0; mi < 2; mi++)
#pragma unroll
                for (int nj = 0; nj < 4; nj++) {
                    fin[mi][nj][0] = fmaf(tmp[mi][nj][0], s2[nj].x, fin[mi][nj][0]);
                    fin[mi][nj][1] = fmaf(tmp[mi][nj][1], s2[nj].y, fin[mi][nj][1]);
                    fin[mi][nj][2] = fmaf(tmp[mi][nj][2], s2[nj].x, fin[mi][nj][2]);
                    fin[mi][nj][3] = fmaf(tmp[mi][nj][3], s2[nj].y, fin[mi][nj][3]);
                }
        }
    }

    // ---- epilogue ----
    const int er = m0 + warp_m * 32 + (lane >> 2);
    const int ec = n0 + ecl;
#pragma unroll
    for (int mi = 0; mi < 2; mi++) {
#pragma unroll
        for (int nj = 0; nj < 4; nj++) {
            float* p0 = C + (size_t)(er + mi * 16) * N + ec + nj * 8;
            float* p1 = C + (size_t)(er + mi * 16 + 8) * N + ec + nj * 8;
            *(float2*)p0 = make_float2(fin[mi][nj][0], fin[mi][nj][1]);
            *(float2*)p1 = make_float2(fin[mi][nj][2], fin[mi][nj][3]);
        }
    }
}

// ---------------- launch ----------------

extern "C" void kernel_launch(void* const* d_in, const int* in_sizes, int n_in,
                              void* d_out, int out_size) {
    const float* X  = (const float*)d_in[0];
    const int*   Q  = (const int*)d_in[1];
    const float* AM = (const float*)d_in[2];

    double s0 = (double)in_sizes[0];
    double s1 = (double)in_sizes[1];
    double so = (double)out_size;
    int K = (int)(sqrt(s0 * s1 / so) + 0.5);
    int M = (int)(s0 / K + 0.5);
    int N = (int)(s1 / K + 0.5);
    int nblk = K >> 8;

    int xt4 = (M * K) / 4;
    prep_x_kernel<<<(xt4 + 255) / 256, 256>>>(X, xt4);
    int wt8 = (int)(((long long)N * K) / 8);
    prep_w_kernel<<<(wt8 + 255) / 256, 256>>>(Q, wt8);
    int st = N * nblk;
    prep_s_kernel<<<(st + 255) / 256, 256>>>(AM, N, nblk);

    cudaFuncSetAttribute(gemm_hmma, cudaFuncAttributeMaxDynamicSharedMemorySize, SMEM_B);
    dim3 grid(M / BM, N / BN);   // m fastest: W n-stripe shared via L2 within a wave
    gemm_hmma<<<grid, THREADS, SMEM_B>>>((float*)d_out, M, N, K);
}

// round 10
// speedup vs baseline: 8.7043x; 1.2140x over previous
#include <cuda_runtime.h>
#include <cuda_fp16.h>
#include <math.h>
#include <stdint.h>

typedef unsigned int u32;

// Fixed dataset shapes: M=4096, K=2048, N=32000
#define MAX_M 4096
#define MAX_K 2048
#define MAX_V 32000

// Static device scratch (allocation-free rule)
__device__ __half g_XH[(size_t)MAX_M * MAX_K];   // x rounded to fp16
__device__ __half g_WD[(size_t)MAX_V * MAX_K];   // dequantized weights in fp16

// ---------------- PTX helpers ----------------

static __device__ __forceinline__ u32 smem_u32(const void* p) {
    u32 a;
    asm("{ .reg .u64 t; cvta.to.shared.u64 t, %1; cvt.u32.u64 %0, t; }"
        : "=r"(a) : "l"(p));
    return a;
}

static __device__ __forceinline__ void cp16(u32 d, const void* g) {
    asm volatile("cp.async.cg.shared.global [%0], [%1], 16;"
                 :: "r"(d), "l"(g) : "memory");
}
static __device__ __forceinline__ void cp_commit() {
    asm volatile("cp.async.commit_group;" ::: "memory");
}
static __device__ __forceinline__ void cp_wait1() {
    asm volatile("cp.async.wait_group 1;" ::: "memory");
}

static __device__ __forceinline__ void ldsm4(u32 a, u32& r0, u32& r1, u32& r2, u32& r3) {
    asm volatile("ldmatrix.sync.aligned.m8n8.x4.shared.b16 {%0,%1,%2,%3}, [%4];"
                 : "=r"(r0), "=r"(r1), "=r"(r2), "=r"(r3) : "r"(a));
}

static __device__ __forceinline__ void mma16816(float* c,
                                                u32 a0, u32 a1, u32 a2, u32 a3,
                                                u32 b0, u32 b1) {
    asm volatile(
        "mma.sync.aligned.m16n8k16.row.col.f32.f16.f16.f32 "
        "{%0,%1,%2,%3}, {%4,%5,%6,%7}, {%8,%9}, {%0,%1,%2,%3};"
        : "+f"(c[0]), "+f"(c[1]), "+f"(c[2]), "+f"(c[3])
        : "r"(a0), "r"(a1), "r"(a2), "r"(a3), "r"(b0), "r"(b1));
}

// Full SW128 swizzle for 128B rows (BK=64 f16): conflict-free STS.128 + ldmatrix.
static __device__ __forceinline__ u32 swz(int row, int chunk) {
    return (u32)(row * 128 + ((chunk ^ (row & 7)) << 4));
}

// ---------------- Pre-pass kernels ----------------

__global__ void prep_x_kernel(const float* __restrict__ X, int total4) {
    int i = blockIdx.x * 256 + threadIdx.x;
    if (i >= total4) return;
    float4 v = ((const float4*)X)[i];
    __half h[4];
    h[0] = __float2half_rn(v.x);
    h[1] = __float2half_rn(v.y);
    h[2] = __float2half_rn(v.z);
    h[3] = __float2half_rn(v.w);
    ((uint2*)g_XH)[i] = *(uint2*)h;
}

// Full dequant: w = (q - 127.5) * absmax/127.5, rounded to fp16. 8 elems/thread.
__global__ void prep_w_kernel(const int* __restrict__ Q,
                              const float* __restrict__ AM,
                              int total8, int kdiv8, int nblk) {
    int i = blockIdx.x * 256 + threadIdx.x;
    if (i >= total8) return;
    int row = i / kdiv8;
    int c8 = i - row * kdiv8;
    int kblk = (c8 * 8) >> 8;
    float s = AM[(size_t)row * nblk + kblk] * (1.0f / 127.5f);
    int4 a = ((const int4*)Q)[2 * i];
    int4 b = ((const int4*)Q)[2 * i + 1];
    __half h[8];
    h[0] = __float2half_rn(((float)a.x - 127.5f) * s);
    h[1] = __float2half_rn(((float)a.y - 127.5f) * s);
    h[2] = __float2half_rn(((float)a.z - 127.5f) * s);
    h[3] = __float2half_rn(((float)a.w - 127.5f) * s);
    h[4] = __float2half_rn(((float)b.x - 127.5f) * s);
    h[5] = __float2half_rn(((float)b.y - 127.5f) * s);
    h[6] = __float2half_rn(((float)b.z - 127.5f) * s);
    h[7] = __float2half_rn(((float)b.w - 127.5f) * s);
    ((uint4*)g_WD)[i] = *(uint4*)h;
}

// ---------------- Main GEMM ----------------
// C[M,N] = X(fp16) * W(fp16)^T, plain fp32-accumulate HMMA GEMM.
// CTA 128x128, BK=64, 8 warps (2m x 4n, warp tile 64x32),
// 3-stage cp.async, ONE __syncthreads per BK, 2 CTAs/SM.

#define BM 128
#define BN 128
#define BK 64
#define THREADS 256
#define TILE_XB (BM * 128)         // 16 KB X [128][64] f16
#define TILE_WB (BN * 128)         // 16 KB W [128][64] f16
#define STAGE_B (TILE_XB + TILE_WB)   // 32 KB
#define NSTAGE 3
#define SMEM_B (NSTAGE * STAGE_B)  // 96 KB

__global__ __launch_bounds__(THREADS, 2)
void gemm_hmma(float* __restrict__ C, int M, int N, int K) {
    extern __shared__ char sm[];
    const u32 sb = smem_u32(sm);
    const int tid = threadIdx.x;
    const int wid = tid >> 5;
    const int lane = tid & 31;
    const int m0 = blockIdx.x * BM;
    const int n0 = blockIdx.y * BN;
    const int warp_m = wid >> 2;      // 0..1 (64 rows each)
    const int warp_n = wid & 3;       // 0..3 (32 cols each)

    const size_t baseX = (size_t)m0 * K;
    const size_t baseW = (size_t)n0 * K;

    // cp.async mapping: 8 threads per 128B row; 4 rows per thread per tile
    const int lrow = tid >> 3;        // 0..31
    const int lchk = tid & 7;         // 0..7

    // A ldmatrix lane decode (x4: m16 x k16 per mi)
    const int matA = lane >> 3;
    const int rowA_base = warp_m * 64 + ((matA & 1) << 3) + (lane & 7);
    const int cA_sel = matA >> 1;
    // B ldmatrix lane decode (x4 covers 2 nj x 2 k-halves)
    const int matB = lane >> 3;
    const int rowB_base = warp_n * 32 + ((matB >> 1) << 3) + (lane & 7);
    const int cB_sel = matB & 1;

    float fin[4][4][4];
#pragma unroll
    for (int i = 0; i < 4; i++)
#pragma unroll
        for (int j = 0; j < 4; j++)
#pragma unroll
            for (int e = 0; e < 4; e++) fin[i][j][e] = 0.0f;

    const int NK = K / BK;   // 32

    // ---- prologue: prefetch stages 0,1 ----
#pragma unroll
    for (int ps = 0; ps < NSTAGE - 1; ps++) {
        const int k0 = ps * BK;
        const u32 st = sb + ps * STAGE_B;
#pragma unroll
        for (int t = 0; t < 4; t++) {
            int row = lrow + t * 32;
            u32 sw = swz(row, lchk);
            size_t gx = baseX + (size_t)row * K + k0 + lchk * 8;
            size_t gw = baseW + (size_t)row * K + k0 + lchk * 8;
            cp16(st + sw, g_XH + gx);
            cp16(st + TILE_XB + sw, g_WD + gw);
        }
        cp_commit();
    }

    for (int kt = 0; kt < NK; kt++) {
        const int s = kt % NSTAGE;

        cp_wait1();           // stage kt landed (in-order group completion)
        __syncthreads();      // stage kt visible; stage kt-1 reads complete

        // ---- prefetch stage kt+2 into buffer (kt-1)%3 (now safe) ----
        if (kt + NSTAGE - 1 < NK) {
            const int k0 = (kt + NSTAGE - 1) * BK;
            const u32 st = sb + ((kt + NSTAGE - 1) % NSTAGE) * STAGE_B;
#pragma unroll
            for (int t = 0; t < 4; t++) {
                int row = lrow + t * 32;
                u32 sw = swz(row, lchk);
                size_t gx = baseX + (size_t)row * K + k0 + lchk * 8;
                size_t gw = baseW + (size_t)row * K + k0 + lchk * 8;
                cp16(st + sw, g_XH + gx);
                cp16(st + TILE_XB + sw, g_WD + gw);
            }
        }
        cp_commit();          // unconditional: uniform group accounting

        // ---- compute stage s: 4 k16 sub-steps ----
        const u32 stA = sb + s * STAGE_B;
        const u32 stB = stA + TILE_XB;

#pragma unroll
        for (int ks = 0; ks < 4; ks++) {
            // B frags: one ldsm4 covers 2 nj x 2 k-halves
            u32 bq[4][2];
#pragma unroll
            for (int njp = 0; njp < 2; njp++) {
                u32 off = swz(rowB_base + njp * 16, ks * 2 + cB_sel);
                ldsm4(stB + off, bq[njp * 2][0], bq[njp * 2][1],
                      bq[njp * 2 + 1][0], bq[njp * 2 + 1][1]);
            }
#pragma unroll
            for (int mi = 0; mi < 4; mi++) {
                u32 off = swz(rowA_base + mi * 16, ks * 2 + cA_sel);
                u32 a0, a1, a2, a3;
                ldsm4(stA + off, a0, a1, a2, a3);
#pragma unroll
                for (int nj = 0; nj < 4; nj++)
                    mma16816(fin[mi][nj], a0, a1, a2, a3, bq[nj][0], bq[nj][1]);
            }
        }
    }

    // ---- epilogue ----
    const int er = m0 + warp_m * 64 + (lane >> 2);
    const int ec = n0 + warp_n * 32 + (lane & 3) * 2;
#pragma unroll
    for (int mi = 0; mi < 4; mi++) {
#pragma unroll
        for (int nj = 0; nj < 4; nj++) {
            float* p0 = C + (size_t)(er + mi * 16) * N + ec + nj * 8;
            float* p1 = C + (size_t)(er + mi * 16 + 8) * N + ec + nj * 8;
            *(float2*)p0 = make_float2(fin[mi][nj][0], fin[mi][nj][1]);
            *(float2*)p1 = make_float2(fin[mi][nj][2], fin[mi][nj][3]);
        }
    }
}

// ---------------- launch ----------------

extern "C" void kernel_launch(void* const* d_in, const int* in_sizes, int n_in,
                              void* d_out, int out_size) {
    const float* X  = (const float*)d_in[0];
    const int*   Q  = (const int*)d_in[1];
    const float* AM = (const float*)d_in[2];

    double s0 = (double)in_sizes[0];
    double s1 = (double)in_sizes[1];
    double so = (double)out_size;
    int K = (int)(sqrt(s0 * s1 / so) + 0.5);
    int M = (int)(s0 / K + 0.5);
    int N = (int)(s1 / K + 0.5);
    int nblk = K >> 8;

    int xt4 = (M * K) / 4;
    prep_x_kernel<<<(xt4 + 255) / 256, 256>>>(X, xt4);
    int wt8 = (int)(((long long)N * K) / 8);
    prep_w_kernel<<<(wt8 + 255) / 256, 256>>>(Q, AM, wt8, K / 8, nblk);

    cudaFuncSetAttribute(gemm_hmma, cudaFuncAttributeMaxDynamicSharedMemorySize, SMEM_B);
    dim3 grid(M / BM, N / BN);   // m fastest: W n-stripe shared via L2 within a wave
    gemm_hmma<<<grid, THREADS, SMEM_B>>>((float*)d_out, M, N, K);
}

// round 11
// speedup vs baseline: 9.2402x; 1.0616x over previous
#include <cuda_runtime.h>
#include <cuda_fp16.h>
#include <math.h>
#include <stdint.h>

typedef unsigned int u32;

// Fixed dataset shapes: M=4096, K=2048, N=32000
#define MAX_M 4096
#define MAX_K 2048
#define MAX_V 32000

// Static device scratch (allocation-free rule)
__device__ __half g_XH[(size_t)MAX_M * MAX_K];   // x rounded to fp16
__device__ __half g_WD[(size_t)MAX_V * MAX_K];   // dequantized weights in fp16

// ---------------- PTX helpers ----------------

static __device__ __forceinline__ u32 smem_u32(const void* p) {
    u32 a;
    asm("{ .reg .u64 t; cvta.to.shared.u64 t, %1; cvt.u32.u64 %0, t; }"
        : "=r"(a) : "l"(p));
    return a;
}

static __device__ __forceinline__ void cp16(u32 d, const void* g) {
    asm volatile("cp.async.cg.shared.global [%0], [%1], 16;"
                 :: "r"(d), "l"(g) : "memory");
}
static __device__ __forceinline__ void cp_commit() {
    asm volatile("cp.async.commit_group;" ::: "memory");
}
static __device__ __forceinline__ void cp_wait1() {
    asm volatile("cp.async.wait_group 1;" ::: "memory");
}

static __device__ __forceinline__ void ldsm4(u32 a, u32& r0, u32& r1, u32& r2, u32& r3) {
    asm volatile("ldmatrix.sync.aligned.m8n8.x4.shared.b16 {%0,%1,%2,%3}, [%4];"
                 : "=r"(r0), "=r"(r1), "=r"(r2), "=r"(r3) : "r"(a));
}

static __device__ __forceinline__ void mma16816(float* c,
                                                u32 a0, u32 a1, u32 a2, u32 a3,
                                                u32 b0, u32 b1) {
    asm volatile(
        "mma.sync.aligned.m16n8k16.row.col.f32.f16.f16.f32 "
        "{%0,%1,%2,%3}, {%4,%5,%6,%7}, {%8,%9}, {%0,%1,%2,%3};"
        : "+f"(c[0]), "+f"(c[1]), "+f"(c[2]), "+f"(c[3])
        : "r"(a0), "r"(a1), "r"(a2), "r"(a3), "r"(b0), "r"(b1));
}

// Full SW128 swizzle for 128B rows (BK=64 f16): conflict-free STS.128 + ldmatrix.
static __device__ __forceinline__ u32 swz(int row, int chunk) {
    return (u32)(row * 128 + ((chunk ^ (row & 7)) << 4));
}

// ---------------- Pre-pass kernels ----------------

__global__ void prep_x_kernel(const float* __restrict__ X, int total4) {
    int i = blockIdx.x * 256 + threadIdx.x;
    if (i >= total4) return;
    float4 v = ((const float4*)X)[i];
    __half h[4];
    h[0] = __float2half_rn(v.x);
    h[1] = __float2half_rn(v.y);
    h[2] = __float2half_rn(v.z);
    h[3] = __float2half_rn(v.w);
    ((uint2*)g_XH)[i] = *(uint2*)h;
}

// Full dequant: w = (q - 127.5) * absmax/127.5, rounded to fp16. 8 elems/thread.
__global__ void prep_w_kernel(const int* __restrict__ Q,
                              const float* __restrict__ AM,
                              int total8, int kdiv8, int nblk) {
    int i = blockIdx.x * 256 + threadIdx.x;
    if (i >= total8) return;
    int row = i / kdiv8;
    int c8 = i - row * kdiv8;
    int kblk = (c8 * 8) >> 8;
    float s = AM[(size_t)row * nblk + kblk] * (1.0f / 127.5f);
    int4 a = ((const int4*)Q)[2 * i];
    int4 b = ((const int4*)Q)[2 * i + 1];
    __half h[8];
    h[0] = __float2half_rn(((float)a.x - 127.5f) * s);
    h[1] = __float2half_rn(((float)a.y - 127.5f) * s);
    h[2] = __float2half_rn(((float)a.z - 127.5f) * s);
    h[3] = __float2half_rn(((float)a.w - 127.5f) * s);
    h[4] = __float2half_rn(((float)b.x - 127.5f) * s);
    h[5] = __float2half_rn(((float)b.y - 127.5f) * s);
    h[6] = __float2half_rn(((float)b.z - 127.5f) * s);
    h[7] = __float2half_rn(((float)b.w - 127.5f) * s);
    ((uint4*)g_WD)[i] = *(uint4*)h;
}

// ---------------- Main GEMM ----------------
// C[M,N] = X(fp16) * W(fp16)^T, fp32-accumulate HMMA.
// CTA 128x128, BK=64, 4 warps (2m x 2n), warp tile 64x64 (square -> minimal
// LDSM redundancy), 128 threads, 3-stage cp.async, 2 CTAs/SM.

#define BM 128
#define BN 128
#define BK 64
#define THREADS 128
#define TILE_XB (BM * 128)         // 16 KB X [128][64] f16
#define TILE_WB (BN * 128)         // 16 KB W [128][64] f16
#define STAGE_B (TILE_XB + TILE_WB)   // 32 KB
#define NSTAGE 3
#define SMEM_B (NSTAGE * STAGE_B)  // 96 KB

__global__ __launch_bounds__(THREADS, 2)
void gemm_hmma(float* __restrict__ C, int M, int N, int K) {
    extern __shared__ char sm[];
    const u32 sb = smem_u32(sm);
    const int tid = threadIdx.x;
    const int wid = tid >> 5;
    const int lane = tid & 31;
    const int m0 = blockIdx.x * BM;
    const int n0 = blockIdx.y * BN;
    const int warp_m = wid >> 1;      // 0..1 (64 rows each)
    const int warp_n = wid & 1;       // 0..1 (64 cols each)

    const size_t baseX = (size_t)m0 * K;
    const size_t baseW = (size_t)n0 * K;

    // cp.async mapping: 8 threads per 128B row; 16 rows per pass, 8 passes/tile
    const int lrow = tid >> 3;        // 0..15
    const int lchk = tid & 7;         // 0..7

    // A ldmatrix lane decode (x4: m16 x k16 per mi)
    const int matA = lane >> 3;
    const int rowA_base = warp_m * 64 + ((matA & 1) << 3) + (lane & 7);
    const int cA_sel = matA >> 1;
    // B ldmatrix lane decode (x4 covers 2 nj x 2 k-halves)
    const int matB = lane >> 3;
    const int rowB_base = warp_n * 64 + ((matB >> 1) << 3) + (lane & 7);
    const int cB_sel = matB & 1;

    float fin[4][8][4];
#pragma unroll
    for (int i = 0; i < 4; i++)
#pragma unroll
        for (int j = 0; j < 8; j++)
#pragma unroll
            for (int e = 0; e < 4; e++) fin[i][j][e] = 0.0f;

    const int NK = K / BK;   // 32

    // ---- prologue: prefetch stages 0,1 ----
#pragma unroll
    for (int ps = 0; ps < NSTAGE - 1; ps++) {
        const int k0 = ps * BK;
        const u32 st = sb + ps * STAGE_B;
#pragma unroll
        for (int t = 0; t < 8; t++) {
            int row = lrow + t * 16;
            u32 sw = swz(row, lchk);
            size_t gx = baseX + (size_t)row * K + k0 + lchk * 8;
            size_t gw = baseW + (size_t)row * K + k0 + lchk * 8;
            cp16(st + sw, g_XH + gx);
            cp16(st + TILE_XB + sw, g_WD + gw);
        }
        cp_commit();
    }

    for (int kt = 0; kt < NK; kt++) {
        const int s = kt % NSTAGE;

        cp_wait1();           // stage kt landed (in-order group completion)
        __syncthreads();      // stage kt visible; stage kt-1 reads complete

        // ---- prefetch stage kt+2 into buffer (kt-1)%3 (now safe) ----
        if (kt + NSTAGE - 1 < NK) {
            const int k0 = (kt + NSTAGE - 1) * BK;
            const u32 st = sb + ((kt + NSTAGE - 1) % NSTAGE) * STAGE_B;
#pragma unroll
            for (int t = 0; t < 8; t++) {
                int row = lrow + t * 16;
                u32 sw = swz(row, lchk);
                size_t gx = baseX + (size_t)row * K + k0 + lchk * 8;
                size_t gw = baseW + (size_t)row * K + k0 + lchk * 8;
                cp16(st + sw, g_XH + gx);
                cp16(st + TILE_XB + sw, g_WD + gw);
            }
        }
        cp_commit();          // unconditional: uniform group accounting

        // ---- compute stage s: 4 k16 sub-steps ----
        const u32 stA = sb + s * STAGE_B;
        const u32 stB = stA + TILE_XB;

#pragma unroll
        for (int ks = 0; ks < 4; ks++) {
            // B frags: 8 nj; each ldsm4 covers 2 nj x 2 k-halves
            u32 bq[8][2];
#pragma unroll
            for (int njp = 0; njp < 4; njp++) {
                u32 off = swz(rowB_base + njp * 16, ks * 2 + cB_sel);
                ldsm4(stB + off, bq[njp * 2][0], bq[njp * 2][1],
                      bq[njp * 2 + 1][0], bq[njp * 2 + 1][1]);
            }
#pragma unroll
            for (int mi = 0; mi < 4; mi++) {
                u32 off = swz(rowA_base + mi * 16, ks * 2 + cA_sel);
                u32 a0, a1, a2, a3;
                ldsm4(stA + off, a0, a1, a2, a3);
#pragma unroll
                for (int nj = 0; nj < 8; nj++)
                    mma16816(fin[mi][nj], a0, a1, a2, a3, bq[nj][0], bq[nj][1]);
            }
        }
    }

    // ---- epilogue ----
    const int er = m0 + warp_m * 64 + (lane >> 2);
    const int ec = n0 + warp_n * 64 + (lane & 3) * 2;
#pragma unroll
    for (int mi = 0; mi < 4; mi++) {
#pragma unroll
        for (int nj = 0; nj < 8; nj++) {
            float* p0 = C + (size_t)(er + mi * 16) * N + ec + nj * 8;
            float* p1 = C + (size_t)(er + mi * 16 + 8) * N + ec + nj * 8;
            *(float2*)p0 = make_float2(fin[mi][nj][0], fin[mi][nj][1]);
            *(float2*)p1 = make_float2(fin[mi][nj][2], fin[mi][nj][3]);
        }
    }
}

// ---------------- launch ----------------

extern "C" void kernel_launch(void* const* d_in, const int* in_sizes, int n_in,
                              void* d_out, int out_size) {
    const float* X  = (const float*)d_in[0];
    const int*   Q  = (const int*)d_in[1];
    const float* AM = (const float*)d_in[2];

    double s0 = (double)in_sizes[0];
    double s1 = (double)in_sizes[1];
    double so = (double)out_size;
    int K = (int)(sqrt(s0 * s1 / so) + 0.5);
    int M = (int)(s0 / K + 0.5);
    int N = (int)(s1 / K + 0.5);
    int nblk = K >> 8;

    int xt4 = (M * K) / 4;
    prep_x_kernel<<<(xt4 + 255) / 256, 256>>>(X, xt4);
    int wt8 = (int)(((long long)N * K) / 8);
    prep_w_kernel<<<(wt8 + 255) / 256, 256>>>(Q, AM, wt8, K / 8, nblk);

    cudaFuncSetAttribute(gemm_hmma, cudaFuncAttributeMaxDynamicSharedMemorySize, SMEM_B);
    dim3 grid(M / BM, N / BN);   // m fastest: W n-stripe shared via L2 within a wave
    gemm_hmma<<<grid, THREADS, SMEM_B>>>((float*)d_out, M, N, K);
}